// round 6
// baseline (speedup 1.0000x reference)
#include <cuda_runtime.h>

// AbstractionLayer: B=524288, I=12, R=6, J=2, L=2, V=4
// Packed f32x2, 2 elements/thread (t, t+B/2). Features parked once in
// conflict-free shared memory. R6: 2-way rj blocking (6 sweeps, one rule
// per sweep) -- balances the R4 LDS-crossbar wall (144 LDS) against the R5
// register wall (96 regs @ 4-way). 72 LDS.128/thread, ~64 regs, 8 blocks/SM.
// Softmax max-pass removed (logits bounded); log2e folded into coefs (raw
// ex2.approx); head*body pre-fused; rcp.approx (tol 1e-3).

#define NI 12
#define NR 6
#define NJ 2
#define NL 2
#define NV 4
#define NRJ 12
#define NT 128
#define LOG2E 1.4426950408889634f

typedef unsigned long long u64;

__device__ __forceinline__ u64 pk2(float lo, float hi) {
    u64 r; asm("mov.b64 %0, {%1,%2};" : "=l"(r) : "f"(lo), "f"(hi)); return r;
}
__device__ __forceinline__ void upk2(u64 v, float& lo, float& hi) {
    asm("mov.b64 {%0,%1}, %2;" : "=f"(lo), "=f"(hi) : "l"(v));
}
__device__ __forceinline__ u64 fma2(u64 a, u64 b, u64 c) {
    u64 d; asm("fma.rn.f32x2 %0, %1, %2, %3;" : "=l"(d) : "l"(a), "l"(b), "l"(c)); return d;
}
__device__ __forceinline__ u64 mul2(u64 a, u64 b) {
    u64 d; asm("mul.rn.f32x2 %0, %1, %2;" : "=l"(d) : "l"(a), "l"(b)); return d;
}
__device__ __forceinline__ u64 add2(u64 a, u64 b) {
    u64 d; asm("add.rn.f32x2 %0, %1, %2;" : "=l"(d) : "l"(a), "l"(b)); return d;
}
__device__ __forceinline__ float ex2a(float x) {
    float r; asm("ex2.approx.ftz.f32 %0, %1;" : "=f"(r) : "f"(x)); return r;
}
__device__ __forceinline__ float rcpa(float x) {
    float r; asm("rcp.approx.ftz.f32 %0, %1;" : "=f"(r) : "f"(x)); return r;
}

__global__ __launch_bounds__(NT, 8)
void abstraction_layer_kernel(
    const float* __restrict__ feat,       // [B, I, L]
    const float* __restrict__ templates,  // [R, J, L]
    const float* __restrict__ gammas,     // [R, J, L]
    const float* __restrict__ body_W,     // [R, J, V, L]
    const float* __restrict__ body_b,     // [R, J, V]
    const float* __restrict__ head_W,     // [R, L, V]
    const float* __restrict__ head_b,     // [R, L]
    float* __restrict__ out,              // [B, R, L]
    int B)
{
    __shared__ u64 s_coef[NRJ][4];       // log2e-scaled logit coefs, lane-dup
    __shared__ u64 s_M[NRJ][4];          // fused head*body, lane-dup
    __shared__ u64 s_c[NR * NL];         // fused bias, lane-dup
    __shared__ ulonglong2 sF[NI][NT];    // packed features per (i, thread)

    const int tid = threadIdx.x;

    // ---- one-time parameter fusion (disjoint thread ranges) ----
    if (tid < NRJ) {
        const int r = tid >> 1, j = tid & 1;
        #pragma unroll
        for (int l = 0; l < NL; l++) {
            float g = gammas[(r * NJ + j) * NL + l];
            g = fminf(fmaxf(g, 0.0f), 1.0f);
            const float w = 1.0f - g;
            const float t = templates[(r * NJ + j) * NL + l];
            const float clin  = 2.0f * w * t * LOG2E;
            const float cquad = -w * LOG2E;
            s_coef[tid][l]     = pk2(clin, clin);
            s_coef[tid][2 + l] = pk2(cquad, cquad);
        }
    } else if (tid >= 16 && tid < 16 + 48) {
        const int idx = tid - 16;
        const int l2 = idx & 1, j = (idx >> 1) & 1, l = (idx >> 2) & 1, r = idx >> 3;
        float acc = 0.0f;
        #pragma unroll
        for (int v = 0; v < NV; v++)
            acc += head_W[(r * NL + l) * NV + v] *
                   body_W[((r * NJ + j) * NV + v) * NL + l2];
        s_M[r * NJ + j][l * 2 + l2] = pk2(acc, acc);
    } else if (tid >= 64 && tid < 64 + NR * NL) {
        const int idx = tid - 64;
        const int r = idx >> 1, l = idx & 1;
        float acc = head_b[r * NL + l];
        #pragma unroll
        for (int v = 0; v < NV; v++)
            acc += head_W[(r * NL + l) * NV + v] *
                   (body_b[(r * NJ + 0) * NV + v] + body_b[(r * NJ + 1) * NV + v]);
        s_c[idx] = pk2(acc, acc);
    }
    __syncthreads();

    const int half = B >> 1;
    const int t = blockIdx.x * blockDim.x + tid;
    if (t >= half) return;

    // ---- load features of elements (t, t+half), pack into private smem ----
    {
        const float4* fa = reinterpret_cast<const float4*>(feat + (size_t)t * (NI * NL));
        const float4* fb = reinterpret_cast<const float4*>(feat + (size_t)(t + half) * (NI * NL));
        #pragma unroll
        for (int k = 0; k < 6; k++) {
            const float4 a = fa[k];
            const float4 b = fb[k];
            sF[2 * k][tid]     = make_ulonglong2(pk2(a.x, b.x), pk2(a.y, b.y));
            sF[2 * k + 1][tid] = make_ulonglong2(pk2(a.z, b.z), pk2(a.w, b.w));
        }
    }

    float* o1 = out + (size_t)t * (NR * NL);
    float* o2 = out + (size_t)(t + half) * (NR * NL);

    // ---- 6 sweeps, one rule (= 2 rj) each: features read once per sweep ----
    #pragma unroll 1
    for (int s = 0; s < NR; s++) {
        const int rjb = 2 * s;

        u64 C0[2], C1[2], C2[2], C3[2];
        #pragma unroll
        for (int k = 0; k < 2; k++) {
            C0[k] = s_coef[rjb + k][0];
            C1[k] = s_coef[rjb + k][1];
            C2[k] = s_coef[rjb + k][2];
            C3[k] = s_coef[rjb + k][3];
        }

        u64 se[2], n0[2], n1[2];
        #pragma unroll
        for (int k = 0; k < 2; k++) { se[k] = 0ULL; n0[k] = 0ULL; n1[k] = 0ULL; }

        #pragma unroll 4
        for (int i = 0; i < NI; i++) {
            const ulonglong2 F = sF[i][tid];          // one LDS.128 per i
            #pragma unroll
            for (int k = 0; k < 2; k++) {
                const u64 t1 = fma2(C2[k], F.x, C0[k]);   // f0*(c0+c2*f0)
                const u64 t2 = fma2(C3[k], F.y, C1[k]);   // + f1*(c1+c3*f1)
                const u64 lg = fma2(F.x, t1, mul2(F.y, t2));
                float llo, lhi; upk2(lg, llo, lhi);
                const u64 e = pk2(ex2a(llo), ex2a(lhi));
                se[k] = add2(se[k], e);
                n0[k] = fma2(e, F.x, n0[k]);
                n1[k] = fma2(e, F.y, n1[k]);
            }
        }

        // epilogue: rule s (output dims 2s, 2s+1)
        u64 A0 = s_c[2 * s + 0];
        u64 A1 = s_c[2 * s + 1];
        #pragma unroll
        for (int k = 0; k < 2; k++) {
            const int rj = rjb + k;
            float slo, shi; upk2(se[k], slo, shi);
            const u64 rinv = pk2(rcpa(slo), rcpa(shi));
            const u64 s0 = mul2(n0[k], rinv);
            const u64 s1 = mul2(n1[k], rinv);
            A0 = fma2(s_M[rj][0], s0, fma2(s_M[rj][1], s1, A0));
            A1 = fma2(s_M[rj][2], s0, fma2(s_M[rj][3], s1, A1));
        }

        float x0, x1, y0, y1;
        upk2(A0, x0, x1);
        upk2(A1, y0, y1);
        *reinterpret_cast<float2*>(o1 + s * 2) = make_float2(x0, y0);
        *reinterpret_cast<float2*>(o2 + s * 2) = make_float2(x1, y1);
    }
}

extern "C" void kernel_launch(void* const* d_in, const int* in_sizes, int n_in,
                              void* d_out, int out_size) {
    const float* feat      = (const float*)d_in[0];
    const float* templates = (const float*)d_in[1];
    const float* gammas    = (const float*)d_in[2];
    const float* body_W    = (const float*)d_in[3];
    const float* body_b    = (const float*)d_in[4];
    const float* head_W    = (const float*)d_in[5];
    const float* head_b    = (const float*)d_in[6];
    float* out = (float*)d_out;

    const int B = in_sizes[0] / (NI * NL);
    const int half = B >> 1;
    const int blocks = (half + NT - 1) / NT;
    abstraction_layer_kernel<<<blocks, NT>>>(
        feat, templates, gammas, body_W, body_b, head_W, head_b, out, B);
}

// round 7
// speedup vs baseline: 1.1114x; 1.1114x over previous
#include <cuda_runtime.h>

// AbstractionLayer: B=524288, I=12, R=6, J=2, L=2, V=4
// Packed f32x2, 2 elements/thread (t, t+B/2). Features parked once in
// conflict-free shared memory; 4-way rj blocking (3 sweeps, 36 LDS.128/thd)
// -- R5 shape, empirically best (LDS traffic + per-i ILP dominate, not occ).
// R7: i-loop unroll 4 (cap front-batched LDS regs) + launch_bounds(128,6)
// to lift occupancy 5 -> 6 blocks/SM without changing the instr stream.
// Softmax max-pass removed (logits bounded); log2e folded into coefs (raw
// ex2.approx); head*body pre-fused; rcp.approx (tol 1e-3).

#define NI 12
#define NR 6
#define NJ 2
#define NL 2
#define NV 4
#define NRJ 12
#define NT 128
#define LOG2E 1.4426950408889634f

typedef unsigned long long u64;

__device__ __forceinline__ u64 pk2(float lo, float hi) {
    u64 r; asm("mov.b64 %0, {%1,%2};" : "=l"(r) : "f"(lo), "f"(hi)); return r;
}
__device__ __forceinline__ void upk2(u64 v, float& lo, float& hi) {
    asm("mov.b64 {%0,%1}, %2;" : "=f"(lo), "=f"(hi) : "l"(v));
}
__device__ __forceinline__ u64 fma2(u64 a, u64 b, u64 c) {
    u64 d; asm("fma.rn.f32x2 %0, %1, %2, %3;" : "=l"(d) : "l"(a), "l"(b), "l"(c)); return d;
}
__device__ __forceinline__ u64 mul2(u64 a, u64 b) {
    u64 d; asm("mul.rn.f32x2 %0, %1, %2;" : "=l"(d) : "l"(a), "l"(b)); return d;
}
__device__ __forceinline__ u64 add2(u64 a, u64 b) {
    u64 d; asm("add.rn.f32x2 %0, %1, %2;" : "=l"(d) : "l"(a), "l"(b)); return d;
}
__device__ __forceinline__ float ex2a(float x) {
    float r; asm("ex2.approx.ftz.f32 %0, %1;" : "=f"(r) : "f"(x)); return r;
}
__device__ __forceinline__ float rcpa(float x) {
    float r; asm("rcp.approx.ftz.f32 %0, %1;" : "=f"(r) : "f"(x)); return r;
}

__global__ __launch_bounds__(NT, 6)
void abstraction_layer_kernel(
    const float* __restrict__ feat,       // [B, I, L]
    const float* __restrict__ templates,  // [R, J, L]
    const float* __restrict__ gammas,     // [R, J, L]
    const float* __restrict__ body_W,     // [R, J, V, L]
    const float* __restrict__ body_b,     // [R, J, V]
    const float* __restrict__ head_W,     // [R, L, V]
    const float* __restrict__ head_b,     // [R, L]
    float* __restrict__ out,              // [B, R, L]
    int B)
{
    __shared__ u64 s_coef[NRJ][4];       // log2e-scaled logit coefs, lane-dup
    __shared__ u64 s_M[NRJ][4];          // fused head*body, lane-dup
    __shared__ u64 s_c[NR * NL];         // fused bias, lane-dup
    __shared__ ulonglong2 sF[NI][NT];    // packed features per (i, thread)

    const int tid = threadIdx.x;

    // ---- one-time parameter fusion (disjoint thread ranges) ----
    if (tid < NRJ) {
        const int r = tid >> 1, j = tid & 1;
        #pragma unroll
        for (int l = 0; l < NL; l++) {
            float g = gammas[(r * NJ + j) * NL + l];
            g = fminf(fmaxf(g, 0.0f), 1.0f);
            const float w = 1.0f - g;
            const float t = templates[(r * NJ + j) * NL + l];
            const float clin  = 2.0f * w * t * LOG2E;
            const float cquad = -w * LOG2E;
            s_coef[tid][l]     = pk2(clin, clin);
            s_coef[tid][2 + l] = pk2(cquad, cquad);
        }
    } else if (tid >= 16 && tid < 16 + 48) {
        const int idx = tid - 16;
        const int l2 = idx & 1, j = (idx >> 1) & 1, l = (idx >> 2) & 1, r = idx >> 3;
        float acc = 0.0f;
        #pragma unroll
        for (int v = 0; v < NV; v++)
            acc += head_W[(r * NL + l) * NV + v] *
                   body_W[((r * NJ + j) * NV + v) * NL + l2];
        s_M[r * NJ + j][l * 2 + l2] = pk2(acc, acc);
    } else if (tid >= 64 && tid < 64 + NR * NL) {
        const int idx = tid - 64;
        const int r = idx >> 1, l = idx & 1;
        float acc = head_b[r * NL + l];
        #pragma unroll
        for (int v = 0; v < NV; v++)
            acc += head_W[(r * NL + l) * NV + v] *
                   (body_b[(r * NJ + 0) * NV + v] + body_b[(r * NJ + 1) * NV + v]);
        s_c[idx] = pk2(acc, acc);
    }
    __syncthreads();

    const int half = B >> 1;
    const int t = blockIdx.x * blockDim.x + tid;
    if (t >= half) return;

    // ---- load features of elements (t, t+half), pack into private smem ----
    {
        const float4* fa = reinterpret_cast<const float4*>(feat + (size_t)t * (NI * NL));
        const float4* fb = reinterpret_cast<const float4*>(feat + (size_t)(t + half) * (NI * NL));
        #pragma unroll
        for (int k = 0; k < 6; k++) {
            const float4 a = fa[k];
            const float4 b = fb[k];
            sF[2 * k][tid]     = make_ulonglong2(pk2(a.x, b.x), pk2(a.y, b.y));
            sF[2 * k + 1][tid] = make_ulonglong2(pk2(a.z, b.z), pk2(a.w, b.w));
        }
    }

    float* o1 = out + (size_t)t * (NR * NL);
    float* o2 = out + (size_t)(t + half) * (NR * NL);

    // ---- 3 sweeps, 4 (r,j) pairs each: features read once per sweep ----
    #pragma unroll 1
    for (int s = 0; s < 3; s++) {
        const int rjb = 4 * s;

        u64 C0[4], C1[4], C2[4], C3[4];
        #pragma unroll
        for (int k = 0; k < 4; k++) {
            C0[k] = s_coef[rjb + k][0];
            C1[k] = s_coef[rjb + k][1];
            C2[k] = s_coef[rjb + k][2];
            C3[k] = s_coef[rjb + k][3];
        }

        u64 se[4], n0[4], n1[4];
        #pragma unroll
        for (int k = 0; k < 4; k++) { se[k] = 0ULL; n0[k] = 0ULL; n1[k] = 0ULL; }

        #pragma unroll 4
        for (int i = 0; i < NI; i++) {
            const ulonglong2 F = sF[i][tid];          // one LDS.128 per i
            #pragma unroll
            for (int k = 0; k < 4; k++) {
                const u64 t1 = fma2(C2[k], F.x, C0[k]);   // f0*(c0+c2*f0)
                const u64 t2 = fma2(C3[k], F.y, C1[k]);   // + f1*(c1+c3*f1)
                const u64 lg = fma2(F.x, t1, mul2(F.y, t2));
                float llo, lhi; upk2(lg, llo, lhi);
                const u64 e = pk2(ex2a(llo), ex2a(lhi));
                se[k] = add2(se[k], e);
                n0[k] = fma2(e, F.x, n0[k]);
                n1[k] = fma2(e, F.y, n1[k]);
            }
        }

        // epilogue: rules 2s and 2s+1 (bias indices 4s..4s+3)
        u64 A0 = s_c[4 * s + 0], A1 = s_c[4 * s + 1];
        u64 A2 = s_c[4 * s + 2], A3 = s_c[4 * s + 3];
        #pragma unroll
        for (int k = 0; k < 4; k++) {
            const int rj = rjb + k;
            float slo, shi; upk2(se[k], slo, shi);
            const u64 rinv = pk2(rcpa(slo), rcpa(shi));
            const u64 s0 = mul2(n0[k], rinv);
            const u64 s1 = mul2(n1[k], rinv);
            if (k < 2) {
                A0 = fma2(s_M[rj][0], s0, fma2(s_M[rj][1], s1, A0));
                A1 = fma2(s_M[rj][2], s0, fma2(s_M[rj][3], s1, A1));
            } else {
                A2 = fma2(s_M[rj][0], s0, fma2(s_M[rj][1], s1, A2));
                A3 = fma2(s_M[rj][2], s0, fma2(s_M[rj][3], s1, A3));
            }
        }

        float x0, x1, y0, y1;
        upk2(A0, x0, x1); upk2(A1, y0, y1);
        *reinterpret_cast<float2*>(o1 + (2 * s) * 2)     = make_float2(x0, y0);
        *reinterpret_cast<float2*>(o2 + (2 * s) * 2)     = make_float2(x1, y1);
        upk2(A2, x0, x1); upk2(A3, y0, y1);
        *reinterpret_cast<float2*>(o1 + (2 * s + 1) * 2) = make_float2(x0, y0);
        *reinterpret_cast<float2*>(o2 + (2 * s + 1) * 2) = make_float2(x1, y1);
    }
}

extern "C" void kernel_launch(void* const* d_in, const int* in_sizes, int n_in,
                              void* d_out, int out_size) {
    const float* feat      = (const float*)d_in[0];
    const float* templates = (const float*)d_in[1];
    const float* gammas    = (const float*)d_in[2];
    const float* body_W    = (const float*)d_in[3];
    const float* body_b    = (const float*)d_in[4];
    const float* head_W    = (const float*)d_in[5];
    const float* head_b    = (const float*)d_in[6];
    float* out = (float*)d_out;

    const int B = in_sizes[0] / (NI * NL);
    const int half = B >> 1;
    const int blocks = (half + NT - 1) / NT;
    abstraction_layer_kernel<<<blocks, NT>>>(
        feat, templates, gammas, body_W, body_b, head_W, head_b, out, B);
}

// round 8
// speedup vs baseline: 1.2699x; 1.1425x over previous
#include <cuda_runtime.h>

// AbstractionLayer: B=524288, I=12, R=6, J=2, L=2, V=4
// Packed f32x2, 2 elements/thread (t, t+B/2). R8: features held in
// REGISTERS for the whole kernel (24 packed u64 = 48 regs), ZERO inner-loop
// shared-memory traffic (the LDS crossbar + front-batched load regs were
// the real cost of the smem park). One (r,j) per sweep (12 sweeps) keeps
// the per-sweep working set at 4 coefs + 3 accums -> ~80 regs, 6 blocks/SM.
// ILP comes from the fully unrolled i-loop (24 independent ex2 per sweep).
// Softmax max-pass removed (logits bounded); log2e folded into coefs (raw
// ex2.approx); head*body pre-fused; rcp.approx (tol 1e-3).

#define NI 12
#define NR 6
#define NJ 2
#define NL 2
#define NV 4
#define NRJ 12
#define NT 128
#define LOG2E 1.4426950408889634f

typedef unsigned long long u64;

__device__ __forceinline__ u64 pk2(float lo, float hi) {
    u64 r; asm("mov.b64 %0, {%1,%2};" : "=l"(r) : "f"(lo), "f"(hi)); return r;
}
__device__ __forceinline__ void upk2(u64 v, float& lo, float& hi) {
    asm("mov.b64 {%0,%1}, %2;" : "=f"(lo), "=f"(hi) : "l"(v));
}
__device__ __forceinline__ u64 fma2(u64 a, u64 b, u64 c) {
    u64 d; asm("fma.rn.f32x2 %0, %1, %2, %3;" : "=l"(d) : "l"(a), "l"(b), "l"(c)); return d;
}
__device__ __forceinline__ u64 mul2(u64 a, u64 b) {
    u64 d; asm("mul.rn.f32x2 %0, %1, %2;" : "=l"(d) : "l"(a), "l"(b)); return d;
}
__device__ __forceinline__ u64 add2(u64 a, u64 b) {
    u64 d; asm("add.rn.f32x2 %0, %1, %2;" : "=l"(d) : "l"(a), "l"(b)); return d;
}
__device__ __forceinline__ float ex2a(float x) {
    float r; asm("ex2.approx.ftz.f32 %0, %1;" : "=f"(r) : "f"(x)); return r;
}
__device__ __forceinline__ float rcpa(float x) {
    float r; asm("rcp.approx.ftz.f32 %0, %1;" : "=f"(r) : "f"(x)); return r;
}

__global__ __launch_bounds__(NT, 6)
void abstraction_layer_kernel(
    const float* __restrict__ feat,       // [B, I, L]
    const float* __restrict__ templates,  // [R, J, L]
    const float* __restrict__ gammas,     // [R, J, L]
    const float* __restrict__ body_W,     // [R, J, V, L]
    const float* __restrict__ body_b,     // [R, J, V]
    const float* __restrict__ head_W,     // [R, L, V]
    const float* __restrict__ head_b,     // [R, L]
    float* __restrict__ out,              // [B, R, L]
    int B)
{
    __shared__ u64 s_coef[NRJ][4];       // log2e-scaled logit coefs, lane-dup
    __shared__ u64 s_M[NRJ][4];          // fused head*body, lane-dup
    __shared__ u64 s_c[NR * NL];         // fused bias, lane-dup

    const int tid = threadIdx.x;

    // ---- one-time parameter fusion (disjoint thread ranges) ----
    if (tid < NRJ) {
        const int r = tid >> 1, j = tid & 1;
        #pragma unroll
        for (int l = 0; l < NL; l++) {
            float g = gammas[(r * NJ + j) * NL + l];
            g = fminf(fmaxf(g, 0.0f), 1.0f);
            const float w = 1.0f - g;
            const float t = templates[(r * NJ + j) * NL + l];
            const float clin  = 2.0f * w * t * LOG2E;
            const float cquad = -w * LOG2E;
            s_coef[tid][l]     = pk2(clin, clin);
            s_coef[tid][2 + l] = pk2(cquad, cquad);
        }
    } else if (tid >= 16 && tid < 16 + 48) {
        const int idx = tid - 16;
        const int l2 = idx & 1, j = (idx >> 1) & 1, l = (idx >> 2) & 1, r = idx >> 3;
        float acc = 0.0f;
        #pragma unroll
        for (int v = 0; v < NV; v++)
            acc += head_W[(r * NL + l) * NV + v] *
                   body_W[((r * NJ + j) * NV + v) * NL + l2];
        s_M[r * NJ + j][l * 2 + l2] = pk2(acc, acc);
    } else if (tid >= 64 && tid < 64 + NR * NL) {
        const int idx = tid - 64;
        const int r = idx >> 1, l = idx & 1;
        float acc = head_b[r * NL + l];
        #pragma unroll
        for (int v = 0; v < NV; v++)
            acc += head_W[(r * NL + l) * NV + v] *
                   (body_b[(r * NJ + 0) * NV + v] + body_b[(r * NJ + 1) * NV + v]);
        s_c[idx] = pk2(acc, acc);
    }
    __syncthreads();

    const int half = B >> 1;
    const int t = blockIdx.x * blockDim.x + tid;
    if (t >= half) return;

    // ---- load features of elements (t, t+half) into REGISTERS, packed ----
    u64 F0[NI], F1[NI];
    {
        const float4* fa = reinterpret_cast<const float4*>(feat + (size_t)t * (NI * NL));
        const float4* fb = reinterpret_cast<const float4*>(feat + (size_t)(t + half) * (NI * NL));
        #pragma unroll
        for (int k = 0; k < 6; k++) {
            const float4 a = fa[k];
            const float4 b = fb[k];
            F0[2 * k]     = pk2(a.x, b.x); F1[2 * k]     = pk2(a.y, b.y);
            F0[2 * k + 1] = pk2(a.z, b.z); F1[2 * k + 1] = pk2(a.w, b.w);
        }
    }

    float* o1 = out + (size_t)t * (NR * NL);
    float* o2 = out + (size_t)(t + half) * (NR * NL);

    // ---- 12 sweeps, one (r,j) each; features stay in registers ----
    #pragma unroll 1
    for (int r = 0; r < NR; r++) {
        u64 A0 = s_c[2 * r + 0];
        u64 A1 = s_c[2 * r + 1];

        #pragma unroll 1
        for (int j = 0; j < NJ; j++) {
            const int rj = 2 * r + j;
            const u64 c0 = s_coef[rj][0], c1 = s_coef[rj][1];
            const u64 c2 = s_coef[rj][2], c3 = s_coef[rj][3];

            u64 se = 0ULL, n0 = 0ULL, n1 = 0ULL;
            #pragma unroll
            for (int i = 0; i < NI; i++) {
                const u64 t1 = fma2(c2, F0[i], c0);   // f0*(c0+c2*f0)
                const u64 t2 = fma2(c3, F1[i], c1);   // + f1*(c1+c3*f1)
                const u64 lg = fma2(F0[i], t1, mul2(F1[i], t2));
                float llo, lhi; upk2(lg, llo, lhi);
                const u64 e = pk2(ex2a(llo), ex2a(lhi));
                se = add2(se, e);
                n0 = fma2(e, F0[i], n0);
                n1 = fma2(e, F1[i], n1);
            }

            float slo, shi; upk2(se, slo, shi);
            const u64 rinv = pk2(rcpa(slo), rcpa(shi));
            const u64 s0 = mul2(n0, rinv);
            const u64 s1 = mul2(n1, rinv);

            A0 = fma2(s_M[rj][0], s0, fma2(s_M[rj][1], s1, A0));
            A1 = fma2(s_M[rj][2], s0, fma2(s_M[rj][3], s1, A1));
        }

        float x0, x1, y0, y1;
        upk2(A0, x0, x1);
        upk2(A1, y0, y1);
        *reinterpret_cast<float2*>(o1 + r * 2) = make_float2(x0, y0);
        *reinterpret_cast<float2*>(o2 + r * 2) = make_float2(x1, y1);
    }
}

extern "C" void kernel_launch(void* const* d_in, const int* in_sizes, int n_in,
                              void* d_out, int out_size) {
    const float* feat      = (const float*)d_in[0];
    const float* templates = (const float*)d_in[1];
    const float* gammas    = (const float*)d_in[2];
    const float* body_W    = (const float*)d_in[3];
    const float* body_b    = (const float*)d_in[4];
    const float* head_W    = (const float*)d_in[5];
    const float* head_b    = (const float*)d_in[6];
    float* out = (float*)d_out;

    const int B = in_sizes[0] / (NI * NL);
    const int half = B >> 1;
    const int blocks = (half + NT - 1) / NT;
    abstraction_layer_kernel<<<blocks, NT>>>(
        feat, templates, gammas, body_W, body_b, head_W, head_b, out, B);
}